// round 11
// baseline (speedup 1.0000x reference)
#include <cuda_runtime.h>
#include <cuda_fp16.h>
#include <cstdint>

#define HH 256
#define WW 256
#define HW 65536
#define C 64
#define O 64
#define B 16
#define NK 4
#define GROUPS 8

#define XST 329                  // xs plane stride (half2): 18*18=324 pad
#define VPL 2176                 // V per-pos plane (half2): 32*68
#define XS_H2 (32 * XST)         // 10528 half2
#define V_OFF XS_H2              // V: 4 pos * VPL half2
#define U_OFF (XS_H2 + 4 * VPL)  // U: 2 * 4096 halves (as half2: 2*2048)
#define SMEM_BYTES ((XS_H2 + 4 * VPL + 2 * 2048) * 4)   // 93312

// ---- scratch ----
__device__ __half g_wu[B * 16 * 4096];   // Winograd U, fragment-ordered per pos
__device__ float g_sum[B * GROUPS];
__device__ float g_sumsq[B * GROUPS];

// Winograd tables: e = d[R0] + SR*d[R1] ; same for columns; fold coeffs AT
__device__ __constant__ int   cR0[4] = {0, 1, 2, 1};
__device__ __constant__ int   cR1[4] = {2, 2, 1, 3};
__device__ __constant__ float cSR[4] = {-1.f, 1.f, -1.f, -1.f};
__device__ __constant__ float cA0[4] = {1.f, 1.f, 1.f, 0.f};
__device__ __constant__ float cA1[4] = {0.f, 1.f, -1.f, -1.f};

__device__ __forceinline__ void mma_f16(float* d, const uint32_t* a,
                                        uint32_t b0, uint32_t b1) {
    asm("mma.sync.aligned.m16n8k16.row.col.f32.f16.f16.f32 "
        "{%0,%1,%2,%3}, {%4,%5,%6,%7}, {%8,%9}, {%0,%1,%2,%3};"
        : "+f"(d[0]), "+f"(d[1]), "+f"(d[2]), "+f"(d[3])
        : "r"(a[0]), "r"(a[1]), "r"(a[2]), "r"(a[3]), "r"(b0), "r"(b1));
}
__device__ __forceinline__ void cp_async16(uint32_t dst, const void* src) {
    asm volatile("cp.async.cg.shared.global [%0], [%1], 16;" :: "r"(dst), "l"(src));
}

// ============================================================================
// Kernel 0: softmax mix + modulate + demodulate -> Winograd U (GwG^T), fp16,
// MMA-A-fragment-ordered: [b][pos16][otile4][kt4][lane32][reg*2+half].
// ============================================================================
__global__ void weight_kernel(const float* __restrict__ mod,
                              const float* __restrict__ kmod,
                              const float* __restrict__ cw) {
    int o = blockIdx.x, b = blockIdx.y, i = threadIdx.x;

    float k0 = kmod[b*NK], k1 = kmod[b*NK+1], k2 = kmod[b*NK+2], k3 = kmod[b*NK+3];
    float mx = fmaxf(fmaxf(k0, k1), fmaxf(k2, k3));
    float e0 = __expf(k0-mx), e1 = __expf(k1-mx), e2 = __expf(k2-mx), e3 = __expf(k3-mx);
    float inv = 1.0f / (e0+e1+e2+e3);
    float a0 = e0*inv, a1 = e1*inv, a2 = e2*inv, a3 = e3*inv;
    float mi = mod[b*C + i] + 1.0f;

    float wv[9], ss = 0.0f;
#pragma unroll
    for (int k = 0; k < 9; k++) {
        int base = (o*C + i)*9 + k;
        const int st = O*C*9;
        float v = a0*cw[base] + a1*cw[st+base] + a2*cw[2*st+base] + a3*cw[3*st+base];
        v *= mi;
        wv[k] = v; ss += v*v;
    }
#pragma unroll
    for (int off = 16; off; off >>= 1) ss += __shfl_xor_sync(~0u, ss, off);
    __shared__ float sh[2];
    if ((i & 31) == 0) sh[i>>5] = ss;
    __syncthreads();
    float innorm = rsqrtf(fmaxf(sh[0] + sh[1], 1e-8f));
#pragma unroll
    for (int k = 0; k < 9; k++) wv[k] *= innorm;

    // U = G w G^T  (4x4)
    float gw[4][3], U[4][4];
#pragma unroll
    for (int j = 0; j < 3; j++) {
        gw[0][j] = wv[j];
        gw[1][j] = 0.5f*(wv[j] + wv[3+j] + wv[6+j]);
        gw[2][j] = 0.5f*(wv[j] - wv[3+j] + wv[6+j]);
        gw[3][j] = wv[6+j];
    }
#pragma unroll
    for (int p = 0; p < 4; p++) {
        U[p][0] = gw[p][0];
        U[p][1] = 0.5f*(gw[p][0] + gw[p][1] + gw[p][2]);
        U[p][2] = 0.5f*(gw[p][0] - gw[p][1] + gw[p][2]);
        U[p][3] = gw[p][2];
    }

    // fragment coords for (o, c=i), mma.m16n8k16 A row-major
    int otile = o >> 4, r = o & 15;
    int kt = i >> 4, kk = i & 15;
    int reg = ((kk >> 3) << 1) | (r >> 3);
    int lane = ((r & 7) << 2) | ((kk & 7) >> 1);
    int half = kk & 1;
    long long base = ((long long)b * 16) * 4096 +
                     ((otile * 4 + kt) * 32 + lane) * 8 + reg * 2 + half;
#pragma unroll
    for (int p = 0; p < 4; p++)
#pragma unroll
        for (int q = 0; q < 4; q++)
            g_wu[base + (p*4 + q) * 4096] = __float2half_rn(U[p][q]);

    if (o == 0 && i < GROUPS) { g_sum[b*GROUPS+i] = 0.0f; g_sumsq[b*GROUPS+i] = 0.0f; }
}

// ============================================================================
// Kernel 1: fused Winograd F(2x2,3x3) conv + GN partial stats.
// grid (16,16,B): 16x16 px region = 8x8 tiles. 8 warps: wo=wid&3 (16 o),
// wt=wid>>2 (32 t). Per pos: GEMM [64o x 64c]x[64c x 64t], A^T M A folded
// into Y register accumulators with {0,+-1} coeffs.
// ============================================================================
__global__ void __launch_bounds__(256, 2)
conv_kernel(const float* __restrict__ x, float* __restrict__ y) {
    extern __shared__ char smem[];
    __half2* xs = (__half2*)smem;
    __half2* V  = xs + XS_H2;
    __half*  Us = (__half*)(xs + U_OFF);
    __shared__ float gsum[GROUPS], gsq[GROUPS];

    int b = blockIdx.z;
    int h0 = blockIdx.y * 16, w0 = blockIdx.x * 16;
    int tid = threadIdx.x, wid = tid >> 5, lane = tid & 31;
    int wo = wid & 3, wt = wid >> 2;
    int l4 = lane & 3, lq = lane >> 2;

    if (tid < GROUPS) { gsum[tid] = 0.0f; gsq[tid] = 0.0f; }

    const __half* wub = g_wu + (long long)b * 16 * 4096;
    uint32_t usm;
    asm("{ .reg .u64 t; cvta.to.shared.u64 t, %1; cvt.u32.u64 %0, t; }"
        : "=r"(usm) : "l"((void*)Us));

    // prefetch U(pos=0) -> buf0
    cp_async16(usm + tid * 16, wub + tid * 8);
    cp_async16(usm + (tid + 256) * 16, wub + (tid + 256) * 8);
    asm volatile("cp.async.commit_group;");

    // ---- stage x halo region as channel-pair half2 (zero padded) ----
    const float* xb = x + (long long)b * C * HW;
    for (int idx = tid; idx < 32 * 324; idx += 256) {
        int ci2 = idx / 324;
        int rem = idx - ci2 * 324;
        int rr = rem / 18, cc = rem - rr * 18;
        int gh = h0 + rr - 1, gw = w0 + cc - 1;
        float v0 = 0.0f, v1 = 0.0f;
        if ((unsigned)gh < HH && (unsigned)gw < WW) {
            const float* p = xb + (2 * ci2) * HW + gh * WW + gw;
            v0 = p[0]; v1 = p[HW];
        }
        xs[ci2 * XST + rr * 18 + cc] = __floats2half2_rn(v0, v1);
    }

    float Y[64];
#pragma unroll
    for (int j = 0; j < 64; j++) Y[j] = 0.0f;

    int c2v = wid * 4 + l4;         // V-build channel-pair
    const __half2* xr = xs + c2v * XST + 2 * lq;

#pragma unroll 1
    for (int pos = 0; pos < 16; pos++) {
        int pi = pos >> 2, pj = pos & 3;

        if (pj == 0) {   // build V for (pi, pj=0..3)
            __syncthreads();
            int r0 = cR0[pi] * 18, r1 = cR1[pi] * 18;
            __half2 srh = __floats2half2_rn(cSR[pi], cSR[pi]);
            __half2* vst = V + c2v * 68 + lq;
#pragma unroll
            for (int i = 0; i < 8; i++) {
                const __half2* dp = xr + (2 * i) * 18;
                __half2 e0 = __hfma2(srh, dp[r1+0], dp[r0+0]);
                __half2 e1 = __hfma2(srh, dp[r1+1], dp[r0+1]);
                __half2 e2 = __hfma2(srh, dp[r1+2], dp[r0+2]);
                __half2 e3 = __hfma2(srh, dp[r1+3], dp[r0+3]);
                vst[0*VPL + 8*i] = __hsub2(e0, e2);
                vst[1*VPL + 8*i] = __hadd2(e1, e2);
                vst[2*VPL + 8*i] = __hsub2(e2, e1);
                vst[3*VPL + 8*i] = __hsub2(e1, e3);
            }
        }

        asm volatile("cp.async.wait_group 0;");
        __syncthreads();
        if (pos < 15) {   // prefetch next U
            const __half* src = wub + (pos + 1) * 4096;
            uint32_t dst = usm + ((pos + 1) & 1) * 8192;
            cp_async16(dst + tid * 16, src + tid * 8);
            cp_async16(dst + (tid + 256) * 16, src + (tid + 256) * 8);
            asm volatile("cp.async.commit_group;");
        }

        // ---- GEMM: M[16] = U(pos) * V(pj) ----
        float M[16];
#pragma unroll
        for (int j = 0; j < 16; j++) M[j] = 0.0f;
        const uint4* ua = (const uint4*)(Us + (pos & 1) * 4096) + (wo * 4) * 32 + lane;
        const __half2* vb = V + pj * VPL + l4 * 68 + wt * 32 + lq;
#pragma unroll
        for (int kt = 0; kt < 4; kt++) {
            uint4 a = ua[kt * 32];
            const __half2* vk = vb + kt * 544;   // kt*8 rows * 68
#pragma unroll
            for (int nt = 0; nt < 4; nt++) {
                uint32_t b0 = *(const uint32_t*)(vk + nt * 8);
                uint32_t b1 = *(const uint32_t*)(vk + 4 * 68 + nt * 8);
                mma_f16(M + nt * 4, (const uint32_t*)&a, b0, b1);
            }
        }

        // ---- fold A^T M A into Y ----
        float su0 = cA0[pi], su1 = cA1[pi], sv0 = cA0[pj], sv1 = cA1[pj];
        float c00 = su0*sv0, c01 = su0*sv1, c10 = su1*sv0, c11 = su1*sv1;
#pragma unroll
        for (int j = 0; j < 16; j++) {
            Y[j]      = fmaf(c00, M[j], Y[j]);
            Y[16 + j] = fmaf(c01, M[j], Y[16 + j]);
            Y[32 + j] = fmaf(c10, M[j], Y[32 + j]);
            Y[48 + j] = fmaf(c11, M[j], Y[48 + j]);
        }
    }

    // ---- epilogue: y stores (float4 = 4 contiguous px) + GN stats ----
    float* yb = y + (long long)b * O * HW;
    float s0 = 0, s1 = 0, q0 = 0, q1 = 0;
#pragma unroll
    for (int u = 0; u < 2; u++) {
#pragma unroll
        for (int nt = 0; nt < 4; nt++) {
            int row = h0 + 2 * (wt * 4 + nt) + u;
#pragma unroll
            for (int rh = 0; rh < 2; rh++) {
                int o = wo * 16 + rh * 8 + lq;
                int jb = nt * 4 + rh * 2;
                float v00 = Y[u*32 + jb];          // v=0, cc=0
                float v10 = Y[u*32 + 16 + jb];     // v=1, cc=0
                float v01 = Y[u*32 + jb + 1];      // v=0, cc=1
                float v11 = Y[u*32 + 16 + jb + 1]; // v=1, cc=1
                float4 f4 = make_float4(v00, v10, v01, v11);
                *(float4*)(yb + o * HW + row * WW + w0 + 4 * l4) = f4;
                float sv = v00 + v10 + v01 + v11;
                float qv = v00*v00 + v10*v10 + v01*v01 + v11*v11;
                if (rh == 0) { s0 += sv; q0 += qv; } else { s1 += sv; q1 += qv; }
            }
        }
    }
#pragma unroll
    for (int off = 16; off; off >>= 1) {
        s0 += __shfl_xor_sync(~0u, s0, off); q0 += __shfl_xor_sync(~0u, q0, off);
        s1 += __shfl_xor_sync(~0u, s1, off); q1 += __shfl_xor_sync(~0u, q1, off);
    }
    if (lane == 0) {
        atomicAdd(&gsum[wo*2],   s0); atomicAdd(&gsq[wo*2],   q0);
        atomicAdd(&gsum[wo*2+1], s1); atomicAdd(&gsq[wo*2+1], q1);
    }
    __syncthreads();
    if (tid < GROUPS) {
        atomicAdd(&g_sum[b * GROUPS + tid], gsum[tid]);
        atomicAdd(&g_sumsq[b * GROUPS + tid], gsq[tid]);
    }
}

// ============================================================================
// Kernel 2: GroupNorm finalize + SiLU, in-place, float4 vectorized.
// ============================================================================
__global__ void norm_kernel(float* __restrict__ y,
                            const float* __restrict__ gamma,
                            const float* __restrict__ beta) {
    long long i = (long long)blockIdx.x * blockDim.x + threadIdx.x;
    long long base = i * 4;
    int cidx = (int)(base >> 16);
    int b = cidx >> 6, c = cidx & 63, g = c >> 3;

    const float invN = 1.0f / (8.0f * HH * WW);
    float mean = g_sum[b * GROUPS + g] * invN;
    float var = g_sumsq[b * GROUPS + g] * invN - mean * mean;
    float istd = rsqrtf(var + 1e-5f);
    float ga = gamma[c], be = beta[c];

    float4 v = *(float4*)&y[base];
    float* vp = &v.x;
#pragma unroll
    for (int k = 0; k < 4; k++) {
        float t = (vp[k] - mean) * istd * ga + be;
        vp[k] = t / (1.0f + __expf(-t));
    }
    *(float4*)&y[base] = v;
}

// ============================================================================
extern "C" void kernel_launch(void* const* d_in, const int* in_sizes, int n_in,
                              void* d_out, int out_size) {
    const float* x     = (const float*)d_in[0];
    const float* mod   = (const float*)d_in[1];
    const float* kmod  = (const float*)d_in[2];
    const float* cw    = (const float*)d_in[3];
    const float* gamma = (const float*)d_in[4];
    const float* beta  = (const float*)d_in[5];
    float* out = (float*)d_out;

    cudaFuncSetAttribute(conv_kernel,
                         cudaFuncAttributeMaxDynamicSharedMemorySize, SMEM_BYTES);

    weight_kernel<<<dim3(O, B), 64>>>(mod, kmod, cw);
    conv_kernel<<<dim3(16, 16, B), 256, SMEM_BYTES>>>(x, out);
    norm_kernel<<<(B * O * HW / 4) / 256, 256>>>(out, gamma, beta);
}